// round 2
// baseline (speedup 1.0000x reference)
#include <cuda_runtime.h>
#include <math.h>

#define WSZ 8
#define NHEAD 4
#define DIM 128
#define NTOK 64
#define HD 32
#define BATCH 32
#define HW 64
#define LSEQ 4096
#define PAD 129
#define SPAD 65
#define RPE_HID 512

__device__ float g_bias[NHEAD * NTOK * NTOK];
__device__ float g_ybuf[(size_t)BATCH * LSEQ * DIM];

// ---------------- Kernel 1: continuous RPE bias table ----------------
__global__ void bias_kernel(const float* __restrict__ w1, const float* __restrict__ b1,
                            const float* __restrict__ w2) {
    __shared__ float ttab[225][NHEAD];
    int tid = threadIdx.x;
    if (tid < 225) {
        int i = tid / 15, j = tid % 15;
        float v0 = (float)(i - 7) / 7.0f * 8.0f;
        float v1 = (float)(j - 7) / 7.0f * 8.0f;
        float inv_l8 = 1.0f / log2f(8.0f);
        float s0 = (v0 > 0.f) ? 1.f : ((v0 < 0.f) ? -1.f : 0.f);
        float s1 = (v1 > 0.f) ? 1.f : ((v1 < 0.f) ? -1.f : 0.f);
        float x0 = s0 * log2f(fabsf(v0) + 1.0f) * inv_l8;
        float x1 = s1 * log2f(fabsf(v1) + 1.0f) * inv_l8;
        float acc0 = 0.f, acc1 = 0.f, acc2 = 0.f, acc3 = 0.f;
        for (int h = 0; h < RPE_HID; h++) {
            float hid = x0 * w1[2 * h] + x1 * w1[2 * h + 1] + b1[h];
            hid = fmaxf(hid, 0.f);
            acc0 += hid * w2[0 * RPE_HID + h];
            acc1 += hid * w2[1 * RPE_HID + h];
            acc2 += hid * w2[2 * RPE_HID + h];
            acc3 += hid * w2[3 * RPE_HID + h];
        }
        ttab[tid][0] = acc0; ttab[tid][1] = acc1;
        ttab[tid][2] = acc2; ttab[tid][3] = acc3;
    }
    __syncthreads();
    for (int e = tid; e < NHEAD * NTOK * NTOK; e += blockDim.x) {
        int h = e >> 12;
        int rem = e & 4095;
        int i = rem >> 6, j = rem & 63;
        int yi = i >> 3, xi = i & 7, yj = j >> 3, xj = j & 7;
        int idx = (yi - yj + 7) * 15 + (xi - xj + 7);
        g_bias[e] = ttab[idx][h];
    }
}

// ---------------- Kernel 2: fused shifted-window attention + LN1 + residual ----------------
// smem layout (floats):
//   xw  [64][129]   input window, later reused as attn-output (PV result)
//   wb  [128][129]  weight staging (qkv chunks, then proj_w)
//   qb,kb,vb [64][129]  (vb later reused as proj output)
//   sb  [64][65]    per-head scores / exp(P)
//   rsum[64], mu[64], rstd[64], regid[64]
__global__ __launch_bounds__(256) void attn_kernel(
    const float* __restrict__ x, const float* __restrict__ qkv_w, const float* __restrict__ qkv_b,
    const float* __restrict__ proj_w, const float* __restrict__ proj_b,
    const float* __restrict__ n1w, const float* __restrict__ n1b)
{
    extern __shared__ float sm[];
    float* xw = sm;
    float* wb = xw + NTOK * PAD;
    float* qb = wb + DIM * PAD;
    float* kb = qb + NTOK * PAD;
    float* vb = kb + NTOK * PAD;
    float* sb = vb + NTOK * PAD;
    float* rsum = sb + NTOK * SPAD;
    float* mu = rsum + 64;
    float* rstd = mu + 64;
    int* regid = (int*)(rstd + 64);

    int tid = threadIdx.x;
    int bx = blockIdx.x;
    int bimg = bx >> 6;
    int wh = (bx >> 3) & 7, ww = bx & 7;
    const float* xbase = x + (size_t)bimg * (LSEQ * DIM);

    // load window (applies -SS roll; source pos == final writeback pos)
    #pragma unroll
    for (int it = 0; it < 8; it++) {
        int e4 = tid + 256 * it;          // 2048 float4
        int t = e4 >> 5;
        int c = (e4 & 31) << 2;
        int ti = t >> 3, tj = t & 7;
        int hh = (wh * 8 + ti + 4) & 63;
        int wwp = (ww * 8 + tj + 4) & 63;
        float4 v = *(const float4*)(xbase + (size_t)((hh << 6) + wwp) * DIM + c);
        float* d = xw + t * PAD + c;
        d[0] = v.x; d[1] = v.y; d[2] = v.z; d[3] = v.w;
    }
    if (tid < 64) {
        int ti = tid >> 3, tj = tid & 7;
        int ah = wh * 8 + ti, aw = ww * 8 + tj;
        int rh = ah < 56 ? 0 : (ah < 60 ? 1 : 2);
        int rw = aw < 56 ? 0 : (aw < 60 ? 1 : 2);
        regid[tid] = rh * 3 + rw;
    }
    __syncthreads();

    int ty = tid >> 4, tx = tid & 15;

    // ---- QKV: 3 chunks of 128 outputs ----
    for (int cidx = 0; cidx < 3; cidx++) {
        const float* wsrc = qkv_w + cidx * DIM * DIM;
        #pragma unroll
        for (int it = 0; it < 16; it++) {
            int e4 = tid + 256 * it;      // 4096 float4
            int r = e4 >> 5;
            int c = (e4 & 31) << 2;
            float4 v = *(const float4*)(wsrc + r * DIM + c);
            float* d = wb + r * PAD + c;
            d[0] = v.x; d[1] = v.y; d[2] = v.z; d[3] = v.w;
        }
        __syncthreads();
        float acc[4][8];
        #pragma unroll
        for (int i = 0; i < 4; i++)
            #pragma unroll
            for (int j = 0; j < 8; j++) acc[i][j] = 0.f;
        #pragma unroll 4
        for (int k = 0; k < DIM; k++) {
            float a[4], bv[8];
            #pragma unroll
            for (int i = 0; i < 4; i++) a[i] = xw[(ty + 16 * i) * PAD + k];
            #pragma unroll
            for (int j = 0; j < 8; j++) bv[j] = wb[(tx + 16 * j) * PAD + k];
            #pragma unroll
            for (int i = 0; i < 4; i++)
                #pragma unroll
                for (int j = 0; j < 8; j++) acc[i][j] += a[i] * bv[j];
        }
        float* dst = (cidx == 0) ? qb : ((cidx == 1) ? kb : vb);
        #pragma unroll
        for (int i = 0; i < 4; i++) {
            int t = ty + 16 * i;
            #pragma unroll
            for (int j = 0; j < 8; j++) {
                int o = tx + 16 * j;
                dst[t * PAD + o] = acc[i][j] + qkv_b[cidx * DIM + o];
            }
        }
        __syncthreads();
    }

    // ---- per-head attention ----
    const float scale = 0.17677669529663687f;  // 32^-0.5
    for (int h = 0; h < NHEAD; h++) {
        int hoff = h * HD;
        // scores S = (q*scale) k^T + bias + mask
        float sacc[4][4];
        #pragma unroll
        for (int i = 0; i < 4; i++)
            #pragma unroll
            for (int j = 0; j < 4; j++) sacc[i][j] = 0.f;
        #pragma unroll 4
        for (int k = 0; k < HD; k++) {
            float a[4], bv[4];
            #pragma unroll
            for (int i = 0; i < 4; i++) a[i] = qb[(ty + 16 * i) * PAD + hoff + k];
            #pragma unroll
            for (int j = 0; j < 4; j++) bv[j] = kb[(tx + 16 * j) * PAD + hoff + k];
            #pragma unroll
            for (int i = 0; i < 4; i++)
                #pragma unroll
                for (int j = 0; j < 4; j++) sacc[i][j] += a[i] * bv[j];
        }
        #pragma unroll
        for (int i = 0; i < 4; i++) {
            int iT = ty + 16 * i;
            int ri = regid[iT];
            #pragma unroll
            for (int j = 0; j < 4; j++) {
                int jT = tx + 16 * j;
                float m = (ri != regid[jT]) ? -100.f : 0.f;
                sb[iT * SPAD + jT] = sacc[i][j] * scale + g_bias[(h * 64 + iT) * 64 + jT] + m;
            }
        }
        __syncthreads();
        // softmax (store unnormalized exp; reciprocal row sums)
        if (tid < 64) {
            float mx = -1e30f;
            for (int j = 0; j < 64; j++) mx = fmaxf(mx, sb[tid * SPAD + j]);
            float s = 0.f;
            for (int j = 0; j < 64; j++) {
                float e = __expf(sb[tid * SPAD + j] - mx);
                sb[tid * SPAD + j] = e;
                s += e;
            }
            rsum[tid] = 1.0f / s;
        }
        __syncthreads();
        // out_h = P @ v_h  (divide by rowsum in epilogue); write into xw
        float oacc[4][2];
        #pragma unroll
        for (int i = 0; i < 4; i++) { oacc[i][0] = 0.f; oacc[i][1] = 0.f; }
        #pragma unroll 4
        for (int k = 0; k < 64; k++) {
            float a[4];
            #pragma unroll
            for (int i = 0; i < 4; i++) a[i] = sb[(ty + 16 * i) * SPAD + k];
            float b0 = vb[k * PAD + hoff + tx];
            float b1 = vb[k * PAD + hoff + tx + 16];
            #pragma unroll
            for (int i = 0; i < 4; i++) { oacc[i][0] += a[i] * b0; oacc[i][1] += a[i] * b1; }
        }
        #pragma unroll
        for (int i = 0; i < 4; i++) {
            int t = ty + 16 * i;
            float rs = rsum[t];
            xw[t * PAD + hoff + tx] = oacc[i][0] * rs;
            xw[t * PAD + hoff + tx + 16] = oacc[i][1] * rs;
        }
        __syncthreads();
    }

    // ---- proj GEMM ----
    #pragma unroll
    for (int it = 0; it < 16; it++) {
        int e4 = tid + 256 * it;
        int r = e4 >> 5;
        int c = (e4 & 31) << 2;
        float4 v = *(const float4*)(proj_w + r * DIM + c);
        float* d = wb + r * PAD + c;
        d[0] = v.x; d[1] = v.y; d[2] = v.z; d[3] = v.w;
    }
    __syncthreads();
    {
        float acc[4][8];
        #pragma unroll
        for (int i = 0; i < 4; i++)
            #pragma unroll
            for (int j = 0; j < 8; j++) acc[i][j] = 0.f;
        #pragma unroll 4
        for (int k = 0; k < DIM; k++) {
            float a[4], bv[8];
            #pragma unroll
            for (int i = 0; i < 4; i++) a[i] = xw[(ty + 16 * i) * PAD + k];
            #pragma unroll
            for (int j = 0; j < 8; j++) bv[j] = wb[(tx + 16 * j) * PAD + k];
            #pragma unroll
            for (int i = 0; i < 4; i++)
                #pragma unroll
                for (int j = 0; j < 8; j++) acc[i][j] += a[i] * bv[j];
        }
        #pragma unroll
        for (int i = 0; i < 4; i++) {
            int t = ty + 16 * i;
            #pragma unroll
            for (int j = 0; j < 8; j++) {
                int o = tx + 16 * j;
                vb[t * PAD + o] = acc[i][j] + proj_b[o];   // vb reused as proj output
            }
        }
    }
    __syncthreads();

    // ---- LN1 stats (two-pass) ----
    if (tid < 64) {
        float s = 0.f;
        for (int c = 0; c < DIM; c++) s += vb[tid * PAD + c];
        float m = s * (1.0f / DIM);
        float v = 0.f;
        for (int c = 0; c < DIM; c++) {
            float d = vb[tid * PAD + c] - m;
            v += d * d;
        }
        mu[tid] = m;
        rstd[tid] = rsqrtf(v * (1.0f / DIM) + 1e-5f);
    }
    __syncthreads();

    // ---- y = x + LN(proj) at the (same) unshifted position ----
    float* yb = g_ybuf + (size_t)bimg * (LSEQ * DIM);
    #pragma unroll
    for (int it = 0; it < 8; it++) {
        int e4 = tid + 256 * it;
        int t = e4 >> 5;
        int c = (e4 & 31) << 2;
        int ti = t >> 3, tj = t & 7;
        int hh = (wh * 8 + ti + 4) & 63;
        int wwp = (ww * 8 + tj + 4) & 63;
        size_t goff = (size_t)((hh << 6) + wwp) * DIM + c;
        float4 xv = *(const float4*)(xbase + goff);
        float m = mu[t], r = rstd[t];
        float4 o;
        o.x = xv.x + (vb[t * PAD + c + 0] - m) * r * n1w[c + 0] + n1b[c + 0];
        o.y = xv.y + (vb[t * PAD + c + 1] - m) * r * n1w[c + 1] + n1b[c + 1];
        o.z = xv.z + (vb[t * PAD + c + 2] - m) * r * n1w[c + 2] + n1b[c + 2];
        o.w = xv.w + (vb[t * PAD + c + 3] - m) * r * n1w[c + 3] + n1b[c + 3];
        *(float4*)(yb + goff) = o;
    }
}

// ---------------- Kernel 3: fused MLP + LN2 + residual ----------------
__global__ __launch_bounds__(256) void mlp_kernel(
    const float* __restrict__ fc1w, const float* __restrict__ fc1b,
    const float* __restrict__ fc2w, const float* __restrict__ fc2b,
    const float* __restrict__ n2w, const float* __restrict__ n2b,
    float* __restrict__ out)
{
    extern __shared__ float sm[];
    float* yt = sm;                 // 64*129
    float* wb = yt + NTOK * PAD;    // 128*129
    float* h1 = wb + DIM * PAD;     // 64*129 (later h2)
    float* mu = h1 + NTOK * PAD;
    float* rstd = mu + 64;

    int tid = threadIdx.x;
    size_t tok0 = (size_t)blockIdx.x * 64;
    const float* ysrc = g_ybuf + tok0 * DIM;

    #pragma unroll
    for (int it = 0; it < 8; it++) {
        int e4 = tid + 256 * it;
        int t = e4 >> 5;
        int c = (e4 & 31) << 2;
        float4 v = *(const float4*)(ysrc + t * DIM + c);
        float* d = yt + t * PAD + c;
        d[0] = v.x; d[1] = v.y; d[2] = v.z; d[3] = v.w;
    }
    __syncthreads();

    int ty = tid >> 4, tx = tid & 15;
    float acc[4][8];   // h2 accumulators
    #pragma unroll
    for (int i = 0; i < 4; i++)
        #pragma unroll
        for (int j = 0; j < 8; j++) acc[i][j] = 0.f;

    for (int hc = 0; hc < 4; hc++) {
        // fc1 chunk (rows hc*128..+128)
        const float* w1 = fc1w + (size_t)hc * 128 * DIM;
        #pragma unroll
        for (int it = 0; it < 16; it++) {
            int e4 = tid + 256 * it;
            int r = e4 >> 5;
            int c = (e4 & 31) << 2;
            float4 v = *(const float4*)(w1 + r * DIM + c);
            float* d = wb + r * PAD + c;
            d[0] = v.x; d[1] = v.y; d[2] = v.z; d[3] = v.w;
        }
        __syncthreads();
        // h1c = gelu(yt @ w1^T + b1)
        float hacc[4][8];
        #pragma unroll
        for (int i = 0; i < 4; i++)
            #pragma unroll
            for (int j = 0; j < 8; j++) hacc[i][j] = 0.f;
        #pragma unroll 4
        for (int k = 0; k < DIM; k++) {
            float a[4], bv[8];
            #pragma unroll
            for (int i = 0; i < 4; i++) a[i] = yt[(ty + 16 * i) * PAD + k];
            #pragma unroll
            for (int j = 0; j < 8; j++) bv[j] = wb[(tx + 16 * j) * PAD + k];
            #pragma unroll
            for (int i = 0; i < 4; i++)
                #pragma unroll
                for (int j = 0; j < 8; j++) hacc[i][j] += a[i] * bv[j];
        }
        #pragma unroll
        for (int i = 0; i < 4; i++) {
            int t = ty + 16 * i;
            #pragma unroll
            for (int j = 0; j < 8; j++) {
                int o = tx + 16 * j;
                float v = hacc[i][j] + fc1b[hc * 128 + o];
                float g = 0.5f * v * (1.0f + erff(v * 0.70710678118654752f));
                h1[t * PAD + o] = g;
            }
        }
        __syncthreads();
        // fc2 chunk: wb[c][hh] = fc2w[c][hc*128+hh]
        #pragma unroll
        for (int it = 0; it < 16; it++) {
            int e4 = tid + 256 * it;
            int c = e4 >> 5;
            int hh = (e4 & 31) << 2;
            float4 v = *(const float4*)(fc2w + (size_t)c * 512 + hc * 128 + hh);
            float* d = wb + c * PAD + hh;
            d[0] = v.x; d[1] = v.y; d[2] = v.z; d[3] = v.w;
        }
        __syncthreads();
        // h2 += h1c @ fc2chunk^T
        #pragma unroll 4
        for (int k = 0; k < DIM; k++) {
            float a[4], bv[8];
            #pragma unroll
            for (int i = 0; i < 4; i++) a[i] = h1[(ty + 16 * i) * PAD + k];
            #pragma unroll
            for (int j = 0; j < 8; j++) bv[j] = wb[(tx + 16 * j) * PAD + k];
            #pragma unroll
            for (int i = 0; i < 4; i++)
                #pragma unroll
                for (int j = 0; j < 8; j++) acc[i][j] += a[i] * bv[j];
        }
        __syncthreads();
    }

    // write h2 (+bias) into h1 buffer
    #pragma unroll
    for (int i = 0; i < 4; i++) {
        int t = ty + 16 * i;
        #pragma unroll
        for (int j = 0; j < 8; j++) {
            int o = tx + 16 * j;
            h1[t * PAD + o] = acc[i][j] + fc2b[o];
        }
    }
    __syncthreads();
    if (tid < 64) {
        float s = 0.f;
        for (int c = 0; c < DIM; c++) s += h1[tid * PAD + c];
        float m = s * (1.0f / DIM);
        float v = 0.f;
        for (int c = 0; c < DIM; c++) {
            float d = h1[tid * PAD + c] - m;
            v += d * d;
        }
        mu[tid] = m;
        rstd[tid] = rsqrtf(v * (1.0f / DIM) + 1e-5f);
    }
    __syncthreads();
    float* od = out + tok0 * DIM;
    #pragma unroll
    for (int it = 0; it < 8; it++) {
        int e4 = tid + 256 * it;
        int t = e4 >> 5;
        int c = (e4 & 31) << 2;
        float m = mu[t], r = rstd[t];
        float4 o;
        o.x = yt[t * PAD + c + 0] + (h1[t * PAD + c + 0] - m) * r * n2w[c + 0] + n2b[c + 0];
        o.y = yt[t * PAD + c + 1] + (h1[t * PAD + c + 1] - m) * r * n2w[c + 1] + n2b[c + 1];
        o.z = yt[t * PAD + c + 2] + (h1[t * PAD + c + 2] - m) * r * n2w[c + 2] + n2b[c + 2];
        o.w = yt[t * PAD + c + 3] + (h1[t * PAD + c + 3] - m) * r * n2w[c + 3] + n2b[c + 3];
        *(float4*)(od + t * DIM + c) = o;
    }
}

static const int ATTN_SMEM = (4 * NTOK * PAD + DIM * PAD + NTOK * SPAD + 3 * 64) * 4 + 64 * 4;
static const int MLP_SMEM  = (2 * NTOK * PAD + DIM * PAD + 2 * 64) * 4;

extern "C" void kernel_launch(void* const* d_in, const int* in_sizes, int n_in,
                              void* d_out, int out_size) {
    const float* x      = (const float*)d_in[0];
    const float* qkv_w  = (const float*)d_in[1];
    const float* qkv_b  = (const float*)d_in[2];
    const float* proj_w = (const float*)d_in[3];
    const float* proj_b = (const float*)d_in[4];
    const float* rpe_w1 = (const float*)d_in[5];
    const float* rpe_b1 = (const float*)d_in[6];
    const float* rpe_w2 = (const float*)d_in[7];
    const float* n1w    = (const float*)d_in[8];
    const float* n1b    = (const float*)d_in[9];
    const float* fc1w   = (const float*)d_in[10];
    const float* fc1b   = (const float*)d_in[11];
    const float* fc2w   = (const float*)d_in[12];
    const float* fc2b   = (const float*)d_in[13];
    const float* n2w    = (const float*)d_in[14];
    const float* n2b    = (const float*)d_in[15];
    float* out = (float*)d_out;

    cudaFuncSetAttribute(attn_kernel, cudaFuncAttributeMaxDynamicSharedMemorySize, ATTN_SMEM);
    cudaFuncSetAttribute(mlp_kernel,  cudaFuncAttributeMaxDynamicSharedMemorySize, MLP_SMEM);

    bias_kernel<<<1, 256>>>(rpe_w1, rpe_b1, rpe_w2);
    attn_kernel<<<2048, 256, ATTN_SMEM>>>(x, qkv_w, qkv_b, proj_w, proj_b, n1w, n1b);
    mlp_kernel<<<2048, 256, MLP_SMEM>>>(fc1w, fc1b, fc2w, fc2b, n2w, n2b, out);
}

// round 3
// speedup vs baseline: 1.8446x; 1.8446x over previous
#include <cuda_runtime.h>
#include <math.h>
#include <stdint.h>

#define WSZ 8
#define NHEAD 4
#define DIM 128
#define NTOK 64
#define HD 32
#define BATCH 32
#define HW 64
#define LSEQ 4096
#define PAD 129
#define SPAD 65
#define RPE_HID 512
#define APAD 132   // pad for mma fragment smem tiles (row*132 mod 32 = 4*row)

__device__ float g_bias[NHEAD * NTOK * NTOK];
__device__ float g_ttab[225 * NHEAD];
__device__ float g_ybuf[(size_t)BATCH * LSEQ * DIM];

// ---------------- RPE bias: table (parallel) + scatter ----------------
__global__ void bias_table_kernel(const float* __restrict__ w1, const float* __restrict__ b1,
                                  const float* __restrict__ w2) {
    __shared__ float4 red[128];
    int p = blockIdx.x;            // 0..224
    int tid = threadIdx.x;         // 128 threads
    int i = p / 15, j = p % 15;
    float v0 = (float)(i - 7) / 7.0f * 8.0f;
    float v1 = (float)(j - 7) / 7.0f * 8.0f;
    float inv_l8 = 1.0f / log2f(8.0f);
    float s0 = (v0 > 0.f) ? 1.f : ((v0 < 0.f) ? -1.f : 0.f);
    float s1 = (v1 > 0.f) ? 1.f : ((v1 < 0.f) ? -1.f : 0.f);
    float x0 = s0 * log2f(fabsf(v0) + 1.0f) * inv_l8;
    float x1 = s1 * log2f(fabsf(v1) + 1.0f) * inv_l8;
    float a0 = 0.f, a1 = 0.f, a2 = 0.f, a3 = 0.f;
    #pragma unroll
    for (int r = 0; r < 4; r++) {
        int h = tid + 128 * r;
        float hid = x0 * w1[2 * h] + x1 * w1[2 * h + 1] + b1[h];
        hid = fmaxf(hid, 0.f);
        a0 += hid * w2[0 * RPE_HID + h];
        a1 += hid * w2[1 * RPE_HID + h];
        a2 += hid * w2[2 * RPE_HID + h];
        a3 += hid * w2[3 * RPE_HID + h];
    }
    red[tid] = make_float4(a0, a1, a2, a3);
    __syncthreads();
    for (int s = 64; s > 0; s >>= 1) {
        if (tid < s) {
            float4 o = red[tid + s];
            red[tid].x += o.x; red[tid].y += o.y; red[tid].z += o.z; red[tid].w += o.w;
        }
        __syncthreads();
    }
    if (tid == 0) {
        g_ttab[p * 4 + 0] = red[0].x; g_ttab[p * 4 + 1] = red[0].y;
        g_ttab[p * 4 + 2] = red[0].z; g_ttab[p * 4 + 3] = red[0].w;
    }
}

__global__ void bias_scatter_kernel() {
    int e = blockIdx.x * 256 + threadIdx.x;     // 16384
    int h = e >> 12;
    int rem = e & 4095;
    int i = rem >> 6, j = rem & 63;
    int yi = i >> 3, xi = i & 7, yj = j >> 3, xj = j & 7;
    int idx = (yi - yj + 7) * 15 + (xi - xj + 7);
    g_bias[e] = g_ttab[idx * 4 + h];
}

// ---------------- Kernel 2: fused shifted-window attention + LN1 + residual (FFMA, unchanged) ----------------
__global__ __launch_bounds__(256) void attn_kernel(
    const float* __restrict__ x, const float* __restrict__ qkv_w, const float* __restrict__ qkv_b,
    const float* __restrict__ proj_w, const float* __restrict__ proj_b,
    const float* __restrict__ n1w, const float* __restrict__ n1b)
{
    extern __shared__ float sm[];
    float* xw = sm;
    float* wb = xw + NTOK * PAD;
    float* qb = wb + DIM * PAD;
    float* kb = qb + NTOK * PAD;
    float* vb = kb + NTOK * PAD;
    float* sb = vb + NTOK * PAD;
    float* rsum = sb + NTOK * SPAD;
    float* mu = rsum + 64;
    float* rstd = mu + 64;
    int* regid = (int*)(rstd + 64);

    int tid = threadIdx.x;
    int bx = blockIdx.x;
    int bimg = bx >> 6;
    int wh = (bx >> 3) & 7, ww = bx & 7;
    const float* xbase = x + (size_t)bimg * (LSEQ * DIM);

    #pragma unroll
    for (int it = 0; it < 8; it++) {
        int e4 = tid + 256 * it;
        int t = e4 >> 5;
        int c = (e4 & 31) << 2;
        int ti = t >> 3, tj = t & 7;
        int hh = (wh * 8 + ti + 4) & 63;
        int wwp = (ww * 8 + tj + 4) & 63;
        float4 v = *(const float4*)(xbase + (size_t)((hh << 6) + wwp) * DIM + c);
        float* d = xw + t * PAD + c;
        d[0] = v.x; d[1] = v.y; d[2] = v.z; d[3] = v.w;
    }
    if (tid < 64) {
        int ti = tid >> 3, tj = tid & 7;
        int ah = wh * 8 + ti, aw = ww * 8 + tj;
        int rh = ah < 56 ? 0 : (ah < 60 ? 1 : 2);
        int rw = aw < 56 ? 0 : (aw < 60 ? 1 : 2);
        regid[tid] = rh * 3 + rw;
    }
    __syncthreads();

    int ty = tid >> 4, tx = tid & 15;

    for (int cidx = 0; cidx < 3; cidx++) {
        const float* wsrc = qkv_w + cidx * DIM * DIM;
        #pragma unroll
        for (int it = 0; it < 16; it++) {
            int e4 = tid + 256 * it;
            int r = e4 >> 5;
            int c = (e4 & 31) << 2;
            float4 v = *(const float4*)(wsrc + r * DIM + c);
            float* d = wb + r * PAD + c;
            d[0] = v.x; d[1] = v.y; d[2] = v.z; d[3] = v.w;
        }
        __syncthreads();
        float acc[4][8];
        #pragma unroll
        for (int i = 0; i < 4; i++)
            #pragma unroll
            for (int j = 0; j < 8; j++) acc[i][j] = 0.f;
        #pragma unroll 4
        for (int k = 0; k < DIM; k++) {
            float a[4], bv[8];
            #pragma unroll
            for (int i = 0; i < 4; i++) a[i] = xw[(ty + 16 * i) * PAD + k];
            #pragma unroll
            for (int j = 0; j < 8; j++) bv[j] = wb[(tx + 16 * j) * PAD + k];
            #pragma unroll
            for (int i = 0; i < 4; i++)
                #pragma unroll
                for (int j = 0; j < 8; j++) acc[i][j] += a[i] * bv[j];
        }
        float* dst = (cidx == 0) ? qb : ((cidx == 1) ? kb : vb);
        #pragma unroll
        for (int i = 0; i < 4; i++) {
            int t = ty + 16 * i;
            #pragma unroll
            for (int j = 0; j < 8; j++) {
                int o = tx + 16 * j;
                dst[t * PAD + o] = acc[i][j] + qkv_b[cidx * DIM + o];
            }
        }
        __syncthreads();
    }

    const float scale = 0.17677669529663687f;
    for (int h = 0; h < NHEAD; h++) {
        int hoff = h * HD;
        float sacc[4][4];
        #pragma unroll
        for (int i = 0; i < 4; i++)
            #pragma unroll
            for (int j = 0; j < 4; j++) sacc[i][j] = 0.f;
        #pragma unroll 4
        for (int k = 0; k < HD; k++) {
            float a[4], bv[4];
            #pragma unroll
            for (int i = 0; i < 4; i++) a[i] = qb[(ty + 16 * i) * PAD + hoff + k];
            #pragma unroll
            for (int j = 0; j < 4; j++) bv[j] = kb[(tx + 16 * j) * PAD + hoff + k];
            #pragma unroll
            for (int i = 0; i < 4; i++)
                #pragma unroll
                for (int j = 0; j < 4; j++) sacc[i][j] += a[i] * bv[j];
        }
        #pragma unroll
        for (int i = 0; i < 4; i++) {
            int iT = ty + 16 * i;
            int ri = regid[iT];
            #pragma unroll
            for (int j = 0; j < 4; j++) {
                int jT = tx + 16 * j;
                float m = (ri != regid[jT]) ? -100.f : 0.f;
                sb[iT * SPAD + jT] = sacc[i][j] * scale + g_bias[(h * 64 + iT) * 64 + jT] + m;
            }
        }
        __syncthreads();
        if (tid < 64) {
            float mx = -1e30f;
            for (int j = 0; j < 64; j++) mx = fmaxf(mx, sb[tid * SPAD + j]);
            float s = 0.f;
            for (int j = 0; j < 64; j++) {
                float e = __expf(sb[tid * SPAD + j] - mx);
                sb[tid * SPAD + j] = e;
                s += e;
            }
            rsum[tid] = 1.0f / s;
        }
        __syncthreads();
        float oacc[4][2];
        #pragma unroll
        for (int i = 0; i < 4; i++) { oacc[i][0] = 0.f; oacc[i][1] = 0.f; }
        #pragma unroll 4
        for (int k = 0; k < 64; k++) {
            float a[4];
            #pragma unroll
            for (int i = 0; i < 4; i++) a[i] = sb[(ty + 16 * i) * SPAD + k];
            float b0 = vb[k * PAD + hoff + tx];
            float b1 = vb[k * PAD + hoff + tx + 16];
            #pragma unroll
            for (int i = 0; i < 4; i++) { oacc[i][0] += a[i] * b0; oacc[i][1] += a[i] * b1; }
        }
        #pragma unroll
        for (int i = 0; i < 4; i++) {
            int t = ty + 16 * i;
            float rs = rsum[t];
            xw[t * PAD + hoff + tx] = oacc[i][0] * rs;
            xw[t * PAD + hoff + tx + 16] = oacc[i][1] * rs;
        }
        __syncthreads();
    }

    #pragma unroll
    for (int it = 0; it < 16; it++) {
        int e4 = tid + 256 * it;
        int r = e4 >> 5;
        int c = (e4 & 31) << 2;
        float4 v = *(const float4*)(proj_w + r * DIM + c);
        float* d = wb + r * PAD + c;
        d[0] = v.x; d[1] = v.y; d[2] = v.z; d[3] = v.w;
    }
    __syncthreads();
    {
        float acc[4][8];
        #pragma unroll
        for (int i = 0; i < 4; i++)
            #pragma unroll
            for (int j = 0; j < 8; j++) acc[i][j] = 0.f;
        #pragma unroll 4
        for (int k = 0; k < DIM; k++) {
            float a[4], bv[8];
            #pragma unroll
            for (int i = 0; i < 4; i++) a[i] = xw[(ty + 16 * i) * PAD + k];
            #pragma unroll
            for (int j = 0; j < 8; j++) bv[j] = wb[(tx + 16 * j) * PAD + k];
            #pragma unroll
            for (int i = 0; i < 4; i++)
                #pragma unroll
                for (int j = 0; j < 8; j++) acc[i][j] += a[i] * bv[j];
        }
        #pragma unroll
        for (int i = 0; i < 4; i++) {
            int t = ty + 16 * i;
            #pragma unroll
            for (int j = 0; j < 8; j++) {
                int o = tx + 16 * j;
                vb[t * PAD + o] = acc[i][j] + proj_b[o];
            }
        }
    }
    __syncthreads();

    if (tid < 64) {
        float s = 0.f;
        for (int c = 0; c < DIM; c++) s += vb[tid * PAD + c];
        float m = s * (1.0f / DIM);
        float v = 0.f;
        for (int c = 0; c < DIM; c++) {
            float d = vb[tid * PAD + c] - m;
            v += d * d;
        }
        mu[tid] = m;
        rstd[tid] = rsqrtf(v * (1.0f / DIM) + 1e-5f);
    }
    __syncthreads();

    float* yb = g_ybuf + (size_t)bimg * (LSEQ * DIM);
    #pragma unroll
    for (int it = 0; it < 8; it++) {
        int e4 = tid + 256 * it;
        int t = e4 >> 5;
        int c = (e4 & 31) << 2;
        int ti = t >> 3, tj = t & 7;
        int hh = (wh * 8 + ti + 4) & 63;
        int wwp = (ww * 8 + tj + 4) & 63;
        size_t goff = (size_t)((hh << 6) + wwp) * DIM + c;
        float4 xv = *(const float4*)(xbase + goff);
        float m = mu[t], r = rstd[t];
        float4 o;
        o.x = xv.x + (vb[t * PAD + c + 0] - m) * r * n1w[c + 0] + n1b[c + 0];
        o.y = xv.y + (vb[t * PAD + c + 1] - m) * r * n1w[c + 1] + n1b[c + 1];
        o.z = xv.z + (vb[t * PAD + c + 2] - m) * r * n1w[c + 2] + n1b[c + 2];
        o.w = xv.w + (vb[t * PAD + c + 3] - m) * r * n1w[c + 3] + n1b[c + 3];
        *(float4*)(yb + goff) = o;
    }
}

// ---------------- tf32 MMA helpers ----------------
__device__ __forceinline__ uint32_t f2tf32(float f) {
    uint32_t u;
    asm("cvt.rna.tf32.f32 %0, %1;" : "=r"(u) : "f"(f));
    return u;
}

__device__ __forceinline__ void mma_tf32(float* c, const uint32_t* a, uint32_t b0, uint32_t b1) {
    asm volatile(
        "mma.sync.aligned.m16n8k8.row.col.f32.tf32.tf32.f32 "
        "{%0,%1,%2,%3}, {%4,%5,%6,%7}, {%8,%9}, {%0,%1,%2,%3};"
        : "+f"(c[0]), "+f"(c[1]), "+f"(c[2]), "+f"(c[3])
        : "r"(a[0]), "r"(a[1]), "r"(a[2]), "r"(a[3]), "r"(b0), "r"(b1));
}

// 128x128x128 warp-tiled GEMM: acc[2][8][4] covers a 32(M)x64(N) warp tile.
// A: [128 rows][APAD] smem (fp32; converted to tf32 at load if CVTA).
// B: [128 n][APAD] smem (already tf32-rounded fp32 bits). C += A @ B^T.
template<bool CVTA>
__device__ __forceinline__ void gemm128_tf32(const float* __restrict__ Asm,
                                             const float* __restrict__ Bsm,
                                             float (&acc)[2][8][4],
                                             int rbase, int nbase, int g, int i)
{
    #pragma unroll 4
    for (int ks = 0; ks < 16; ks++) {
        int kc = i + ks * 8;
        uint32_t a[2][4];
        #pragma unroll
        for (int m = 0; m < 2; m++) {
            int r0 = rbase + m * 16 + g;
            float f0 = Asm[r0 * APAD + kc];
            float f1 = Asm[(r0 + 8) * APAD + kc];
            float f2 = Asm[r0 * APAD + kc + 4];
            float f3 = Asm[(r0 + 8) * APAD + kc + 4];
            if (CVTA) {
                a[m][0] = f2tf32(f0); a[m][1] = f2tf32(f1);
                a[m][2] = f2tf32(f2); a[m][3] = f2tf32(f3);
            } else {
                a[m][0] = __float_as_uint(f0); a[m][1] = __float_as_uint(f1);
                a[m][2] = __float_as_uint(f2); a[m][3] = __float_as_uint(f3);
            }
        }
        #pragma unroll
        for (int n = 0; n < 8; n++) {
            int nc = nbase + n * 8 + g;
            uint32_t b0 = __float_as_uint(Bsm[nc * APAD + kc]);
            uint32_t b1 = __float_as_uint(Bsm[nc * APAD + kc + 4]);
            mma_tf32(acc[0][n], a[0], b0, b1);
            mma_tf32(acc[1][n], a[1], b0, b1);
        }
    }
}

// ---------------- Kernel 3: fused MLP + LN2 + residual (tf32 tensor cores) ----------------
// 128 tokens per CTA, 8 warps arranged 4(M) x 2(N) over 128x128 tiles.
__global__ __launch_bounds__(256, 1) void mlp_kernel(
    const float* __restrict__ fc1w, const float* __restrict__ fc1b,
    const float* __restrict__ fc2w, const float* __restrict__ fc2b,
    const float* __restrict__ n2w, const float* __restrict__ n2b,
    float* __restrict__ out)
{
    extern __shared__ float sm[];
    float* Ysm = sm;                       // [128][APAD]  exact fp32 y (residual source + GEMM1 A)
    float* Wsm = Ysm + 128 * APAD;         // [128][APAD]  weight chunk (tf32 bits)
    float* Hsm = Wsm + 128 * APAD;         // [128][APAD]  h1 chunk (tf32) / final h2 (fp32)
    float* ps  = Hsm + 128 * APAD;         // [256] LN partials
    float* muv = ps + 256;                 // [128]
    float* rsv = muv + 128;                // [128]

    int tid = threadIdx.x;
    int wid = tid >> 5;
    int lane = tid & 31;
    int g = lane >> 2;
    int i = lane & 3;
    int warpM = wid >> 1;
    int warpN = wid & 1;
    int rbase = warpM * 32;
    int nbase = warpN * 64;

    size_t tok0 = (size_t)blockIdx.x * 128;
    const float* ysrc = g_ybuf + tok0 * DIM;

    // load Y tile (exact fp32)
    #pragma unroll
    for (int it = 0; it < 16; it++) {
        int e4 = tid + 256 * it;                 // 4096 float4
        int t = e4 >> 5;
        int c = (e4 & 31) << 2;
        float4 v = *(const float4*)(ysrc + (size_t)t * DIM + c);
        float* d = Ysm + t * APAD + c;
        d[0] = v.x; d[1] = v.y; d[2] = v.z; d[3] = v.w;
    }

    float acc2[2][8][4];
    #pragma unroll
    for (int m = 0; m < 2; m++)
        #pragma unroll
        for (int n = 0; n < 8; n++)
            #pragma unroll
            for (int q = 0; q < 4; q++) acc2[m][n][q] = 0.f;

    for (int hc = 0; hc < 4; hc++) {
        __syncthreads();
        // stage fc1 chunk [128 hid][128 k] -> Wsm (tf32-rounded)
        const float* w1 = fc1w + (size_t)hc * 128 * DIM;
        #pragma unroll
        for (int it = 0; it < 16; it++) {
            int e4 = tid + 256 * it;
            int r = e4 >> 5;
            int c = (e4 & 31) << 2;
            float4 v = *(const float4*)(w1 + r * DIM + c);
            float* d = Wsm + r * APAD + c;
            d[0] = __uint_as_float(f2tf32(v.x));
            d[1] = __uint_as_float(f2tf32(v.y));
            d[2] = __uint_as_float(f2tf32(v.z));
            d[3] = __uint_as_float(f2tf32(v.w));
        }
        __syncthreads();

        // GEMM1: h1c = Y @ W1c^T
        float acc1[2][8][4];
        #pragma unroll
        for (int m = 0; m < 2; m++)
            #pragma unroll
            for (int n = 0; n < 8; n++)
                #pragma unroll
                for (int q = 0; q < 4; q++) acc1[m][n][q] = 0.f;
        gemm128_tf32<true>(Ysm, Wsm, acc1, rbase, nbase, g, i);

        // gelu epilogue -> Hsm (tf32-rounded)
        const float is2 = 0.70710678118654752f;
        #pragma unroll
        for (int n = 0; n < 8; n++) {
            int col = nbase + n * 8 + 2 * i;
            float b0f = fc1b[hc * 128 + col];
            float b1f = fc1b[hc * 128 + col + 1];
            #pragma unroll
            for (int m = 0; m < 2; m++) {
                int row = rbase + m * 16 + g;
                float v0 = acc1[m][n][0] + b0f;
                float v1 = acc1[m][n][1] + b1f;
                float v2 = acc1[m][n][2] + b0f;
                float v3 = acc1[m][n][3] + b1f;
                v0 = 0.5f * v0 * (1.0f + erff(v0 * is2));
                v1 = 0.5f * v1 * (1.0f + erff(v1 * is2));
                v2 = 0.5f * v2 * (1.0f + erff(v2 * is2));
                v3 = 0.5f * v3 * (1.0f + erff(v3 * is2));
                Hsm[row * APAD + col]       = __uint_as_float(f2tf32(v0));
                Hsm[row * APAD + col + 1]   = __uint_as_float(f2tf32(v1));
                Hsm[(row + 8) * APAD + col]     = __uint_as_float(f2tf32(v2));
                Hsm[(row + 8) * APAD + col + 1] = __uint_as_float(f2tf32(v3));
            }
        }
        __syncthreads();

        // stage fc2 chunk: Wsm[n][k] = fc2w[n][hc*128 + k] (tf32-rounded)
        #pragma unroll
        for (int it = 0; it < 16; it++) {
            int e4 = tid + 256 * it;
            int r = e4 >> 5;
            int c = (e4 & 31) << 2;
            float4 v = *(const float4*)(fc2w + (size_t)r * 512 + hc * 128 + c);
            float* d = Wsm + r * APAD + c;
            d[0] = __uint_as_float(f2tf32(v.x));
            d[1] = __uint_as_float(f2tf32(v.y));
            d[2] = __uint_as_float(f2tf32(v.z));
            d[3] = __uint_as_float(f2tf32(v.w));
        }
        __syncthreads();

        // GEMM2: acc2 += h1c @ W2c^T
        gemm128_tf32<false>(Hsm, Wsm, acc2, rbase, nbase, g, i);
    }

    __syncthreads();
    // h2 (+bias) -> Hsm (fp32)
    #pragma unroll
    for (int n = 0; n < 8; n++) {
        int col = nbase + n * 8 + 2 * i;
        float b0f = fc2b[col];
        float b1f = fc2b[col + 1];
        #pragma unroll
        for (int m = 0; m < 2; m++) {
            int row = rbase + m * 16 + g;
            Hsm[row * APAD + col]           = acc2[m][n][0] + b0f;
            Hsm[row * APAD + col + 1]       = acc2[m][n][1] + b1f;
            Hsm[(row + 8) * APAD + col]     = acc2[m][n][2] + b0f;
            Hsm[(row + 8) * APAD + col + 1] = acc2[m][n][3] + b1f;
        }
    }
    __syncthreads();

    // LN2 stats: 2 threads per row
    {
        int row = tid >> 1;
        int cb = (tid & 1) * 64;
        float s = 0.f;
        #pragma unroll 8
        for (int c = 0; c < 64; c++) s += Hsm[row * APAD + cb + c];
        ps[tid] = s;
    }
    __syncthreads();
    if (tid < 128) muv[tid] = (ps[2 * tid] + ps[2 * tid + 1]) * (1.0f / DIM);
    __syncthreads();
    {
        int row = tid >> 1;
        int cb = (tid & 1) * 64;
        float m = muv[row];
        float v = 0.f;
        #pragma unroll 8
        for (int c = 0; c < 64; c++) {
            float d = Hsm[row * APAD + cb + c] - m;
            v += d * d;
        }
        ps[tid] = v;
    }
    __syncthreads();
    if (tid < 128) rsv[tid] = rsqrtf((ps[2 * tid] + ps[2 * tid + 1]) * (1.0f / DIM) + 1e-5f);
    __syncthreads();

    // out = y + LN(h2)
    float* od = out + tok0 * DIM;
    #pragma unroll
    for (int it = 0; it < 16; it++) {
        int e4 = tid + 256 * it;
        int t = e4 >> 5;
        int c = (e4 & 31) << 2;
        float m = muv[t], r = rsv[t];
        float4 o;
        o.x = Ysm[t * APAD + c + 0] + (Hsm[t * APAD + c + 0] - m) * r * n2w[c + 0] + n2b[c + 0];
        o.y = Ysm[t * APAD + c + 1] + (Hsm[t * APAD + c + 1] - m) * r * n2w[c + 1] + n2b[c + 1];
        o.z = Ysm[t * APAD + c + 2] + (Hsm[t * APAD + c + 2] - m) * r * n2w[c + 2] + n2b[c + 2];
        o.w = Ysm[t * APAD + c + 3] + (Hsm[t * APAD + c + 3] - m) * r * n2w[c + 3] + n2b[c + 3];
        *(float4*)(od + (size_t)t * DIM + c) = o;
    }
}

static const int ATTN_SMEM = (4 * NTOK * PAD + DIM * PAD + NTOK * SPAD + 3 * 64) * 4 + 64 * 4;
static const int MLP_SMEM  = (3 * 128 * APAD + 256 + 128 + 128) * 4;

extern "C" void kernel_launch(void* const* d_in, const int* in_sizes, int n_in,
                              void* d_out, int out_size) {
    const float* x      = (const float*)d_in[0];
    const float* qkv_w  = (const float*)d_in[1];
    const float* qkv_b  = (const float*)d_in[2];
    const float* proj_w = (const float*)d_in[3];
    const float* proj_b = (const float*)d_in[4];
    const float* rpe_w1 = (const float*)d_in[5];
    const float* rpe_b1 = (const float*)d_in[6];
    const float* rpe_w2 = (const float*)d_in[7];
    const float* n1w    = (const float*)d_in[8];
    const float* n1b    = (const float*)d_in[9];
    const float* fc1w   = (const float*)d_in[10];
    const float* fc1b   = (const float*)d_in[11];
    const float* fc2w   = (const float*)d_in[12];
    const float* fc2b   = (const float*)d_in[13];
    const float* n2w    = (const float*)d_in[14];
    const float* n2b    = (const float*)d_in[15];
    float* out = (float*)d_out;

    cudaFuncSetAttribute(attn_kernel, cudaFuncAttributeMaxDynamicSharedMemorySize, ATTN_SMEM);
    cudaFuncSetAttribute(mlp_kernel,  cudaFuncAttributeMaxDynamicSharedMemorySize, MLP_SMEM);

    bias_table_kernel<<<225, 128>>>(rpe_w1, rpe_b1, rpe_w2);
    bias_scatter_kernel<<<64, 256>>>();
    attn_kernel<<<2048, 256, ATTN_SMEM>>>(x, qkv_w, qkv_b, proj_w, proj_b, n1w, n1b);
    mlp_kernel<<<1024, 256, MLP_SMEM>>>(fc1w, fc1b, fc2w, fc2b, n2w, n2b, out);
}

// round 4
// speedup vs baseline: 3.7199x; 2.0166x over previous
#include <cuda_runtime.h>
#include <math.h>
#include <stdint.h>

#define WSZ 8
#define NHEAD 4
#define DIM 128
#define NTOK 64
#define HD 32
#define BATCH 32
#define HW 64
#define LSEQ 4096
#define RPE_HID 512
#define APAD 132
#define SBP 67
#define VTP 68

__device__ float g_bias[NHEAD * NTOK * NTOK];
__device__ float g_ttab[225 * NHEAD];
__device__ float g_ybuf[(size_t)BATCH * LSEQ * DIM];

// ---------------- tf32 MMA helpers ----------------
__device__ __forceinline__ uint32_t f2tf32(float f) {
    uint32_t u;
    asm("cvt.rna.tf32.f32 %0, %1;" : "=r"(u) : "f"(f));
    return u;
}
__device__ __forceinline__ float rtf32(float f) { return __uint_as_float(f2tf32(f)); }

__device__ __forceinline__ void mma_tf32(float* c, const uint32_t* a, uint32_t b0, uint32_t b1) {
    asm volatile(
        "mma.sync.aligned.m16n8k8.row.col.f32.tf32.tf32.f32 "
        "{%0,%1,%2,%3}, {%4,%5,%6,%7}, {%8,%9}, {%0,%1,%2,%3};"
        : "+f"(c[0]), "+f"(c[1]), "+f"(c[2]), "+f"(c[3])
        : "r"(a[0]), "r"(a[1]), "r"(a[2]), "r"(a[3]), "r"(b0), "r"(b1));
}

// Generic warp GEMM: C[MT*16 x NT*8] += A @ B^T.
// A: [row][lda] smem fp32 (already tf32-rounded bits), rows rbase..; cols aoff+k.
// B: [n][ldb] smem, n rows nbase..; cols boff+k.
template<int MT, int NT, int KS>
__device__ __forceinline__ void wgemm(const float* __restrict__ Asm, int lda, int aoff,
                                      const float* __restrict__ Bsm, int ldb, int boff,
                                      float (&acc)[MT][NT][4], int rbase, int nbase,
                                      int g, int i)
{
    #pragma unroll
    for (int ks = 0; ks < KS; ks++) {
        int kc = i + ks * 8;
        uint32_t a[MT][4];
        #pragma unroll
        for (int m = 0; m < MT; m++) {
            int r0 = rbase + m * 16 + g;
            a[m][0] = __float_as_uint(Asm[r0 * lda + aoff + kc]);
            a[m][1] = __float_as_uint(Asm[(r0 + 8) * lda + aoff + kc]);
            a[m][2] = __float_as_uint(Asm[r0 * lda + aoff + kc + 4]);
            a[m][3] = __float_as_uint(Asm[(r0 + 8) * lda + aoff + kc + 4]);
        }
        #pragma unroll
        for (int n = 0; n < NT; n++) {
            int nc = nbase + n * 8 + g;
            uint32_t b0 = __float_as_uint(Bsm[nc * ldb + boff + kc]);
            uint32_t b1 = __float_as_uint(Bsm[nc * ldb + boff + kc + 4]);
            #pragma unroll
            for (int m = 0; m < MT; m++) mma_tf32(acc[m][n], a[m], b0, b1);
        }
    }
}

// ---------------- RPE bias: table (parallel) + scatter ----------------
__global__ void bias_table_kernel(const float* __restrict__ w1, const float* __restrict__ b1,
                                  const float* __restrict__ w2) {
    __shared__ float4 red[128];
    int p = blockIdx.x;
    int tid = threadIdx.x;
    int i = p / 15, j = p % 15;
    float v0 = (float)(i - 7) / 7.0f * 8.0f;
    float v1 = (float)(j - 7) / 7.0f * 8.0f;
    float inv_l8 = 1.0f / log2f(8.0f);
    float s0 = (v0 > 0.f) ? 1.f : ((v0 < 0.f) ? -1.f : 0.f);
    float s1 = (v1 > 0.f) ? 1.f : ((v1 < 0.f) ? -1.f : 0.f);
    float x0 = s0 * log2f(fabsf(v0) + 1.0f) * inv_l8;
    float x1 = s1 * log2f(fabsf(v1) + 1.0f) * inv_l8;
    float a0 = 0.f, a1 = 0.f, a2 = 0.f, a3 = 0.f;
    #pragma unroll
    for (int r = 0; r < 4; r++) {
        int h = tid + 128 * r;
        float hid = x0 * w1[2 * h] + x1 * w1[2 * h + 1] + b1[h];
        hid = fmaxf(hid, 0.f);
        a0 += hid * w2[0 * RPE_HID + h];
        a1 += hid * w2[1 * RPE_HID + h];
        a2 += hid * w2[2 * RPE_HID + h];
        a3 += hid * w2[3 * RPE_HID + h];
    }
    red[tid] = make_float4(a0, a1, a2, a3);
    __syncthreads();
    for (int s = 64; s > 0; s >>= 1) {
        if (tid < s) {
            float4 o = red[tid + s];
            red[tid].x += o.x; red[tid].y += o.y; red[tid].z += o.z; red[tid].w += o.w;
        }
        __syncthreads();
    }
    if (tid == 0) {
        g_ttab[p * 4 + 0] = red[0].x; g_ttab[p * 4 + 1] = red[0].y;
        g_ttab[p * 4 + 2] = red[0].z; g_ttab[p * 4 + 3] = red[0].w;
    }
}

__global__ void bias_scatter_kernel() {
    int e = blockIdx.x * 256 + threadIdx.x;
    int h = e >> 12;
    int rem = e & 4095;
    int i = rem >> 6, j = rem & 63;
    int yi = i >> 3, xi = i & 7, yj = j >> 3, xj = j & 7;
    int idx = (yi - yj + 7) * 15 + (xi - xj + 7);
    g_bias[e] = g_ttab[idx * 4 + h];
}

// ---------------- Kernel 2: fused shifted-window attention + LN1 + residual (tf32 MMA) ----------------
// smem float offsets:
//   xw  @0      [64][132]   (8448)  -- overlaid by sb4 after QKV
//   wb  @8448   [128][132]  (16896) -- qkv chunks; overlaid by sb4 tail; restaged as proj_w
//   qb  @25344  [64][132]   (8448)  -- overlaid by attn-out after scores
//   kb  @33792  [64][132]   (8448)  -- reused as proj output
//   vt  @42240  [128][68]   (8704)  -- V transposed [dim][tok]
//   rsum4 @50944 [256], regid [64] ints, mu [64], rstd [64]
__global__ __launch_bounds__(256) void attn_kernel(
    const float* __restrict__ x, const float* __restrict__ qkv_w, const float* __restrict__ qkv_b,
    const float* __restrict__ proj_w, const float* __restrict__ proj_b,
    const float* __restrict__ n1w, const float* __restrict__ n1b)
{
    extern __shared__ float sm[];
    float* xw = sm;
    float* sb4 = sm;                 // 4*64*67 = 17152 <= 25344
    float* wb = sm + 8448;
    float* qb = sm + 25344;
    float* ow = qb;
    float* kb = sm + 33792;
    float* vt = sm + 42240;
    float* rsum4 = sm + 50944;
    int* regid = (int*)(rsum4 + 256);
    float* mu = (float*)(regid + 64);
    float* rstd = mu + 64;

    int tid = threadIdx.x;
    int wid = tid >> 5;
    int lane = tid & 31;
    int g = lane >> 2;
    int i = lane & 3;

    int bx = blockIdx.x;
    int bimg = bx >> 6;
    int wh = (bx >> 3) & 7, ww = bx & 7;
    const float* xbase = x + (size_t)bimg * (LSEQ * DIM);

    // ---- load window (rolled by -SS), tf32-rounded (GEMM A only); regid ----
    #pragma unroll
    for (int it = 0; it < 8; it++) {
        int e4 = tid + 256 * it;
        int t = e4 >> 5;
        int c = (e4 & 31) << 2;
        int ti = t >> 3, tj = t & 7;
        int hh = (wh * 8 + ti + 4) & 63;
        int wwp = (ww * 8 + tj + 4) & 63;
        float4 v = *(const float4*)(xbase + (size_t)((hh << 6) + wwp) * DIM + c);
        float* d = xw + t * APAD + c;
        d[0] = rtf32(v.x); d[1] = rtf32(v.y); d[2] = rtf32(v.z); d[3] = rtf32(v.w);
    }
    if (tid < 64) {
        int ti = tid >> 3, tj = tid & 7;
        int ah = wh * 8 + ti, aw = ww * 8 + tj;
        int rh = ah < 56 ? 0 : (ah < 60 ? 1 : 2);
        int rw = aw < 56 ? 0 : (aw < 60 ? 1 : 2);
        regid[tid] = rh * 3 + rw;
    }

    const float scale = 0.17677669529663687f;

    // ---- QKV: 3 GEMMs 64x128x128 ----
    for (int cidx = 0; cidx < 3; cidx++) {
        const float* wsrc = qkv_w + cidx * DIM * DIM;
        #pragma unroll
        for (int it = 0; it < 16; it++) {
            int e4 = tid + 256 * it;
            int r = e4 >> 5;
            int c = (e4 & 31) << 2;
            float4 v = *(const float4*)(wsrc + r * DIM + c);
            float* d = wb + r * APAD + c;
            d[0] = rtf32(v.x); d[1] = rtf32(v.y); d[2] = rtf32(v.z); d[3] = rtf32(v.w);
        }
        __syncthreads();

        float acc[2][4][4];
        #pragma unroll
        for (int m = 0; m < 2; m++)
            #pragma unroll
            for (int n = 0; n < 4; n++)
                #pragma unroll
                for (int q = 0; q < 4; q++) acc[m][n][q] = 0.f;
        int rbase = (wid >> 2) * 32;
        int nbase = (wid & 3) * 32;
        wgemm<2, 4, 16>(xw, APAD, 0, wb, APAD, 0, acc, rbase, nbase, g, i);

        // epilogue
        #pragma unroll
        for (int n = 0; n < 4; n++) {
            int col = nbase + n * 8 + 2 * i;
            float b0f = qkv_b[cidx * DIM + col];
            float b1f = qkv_b[cidx * DIM + col + 1];
            #pragma unroll
            for (int m = 0; m < 2; m++) {
                int row = rbase + m * 16 + g;
                float v0 = acc[m][n][0] + b0f;
                float v1 = acc[m][n][1] + b1f;
                float v2 = acc[m][n][2] + b0f;
                float v3 = acc[m][n][3] + b1f;
                if (cidx == 0) {
                    qb[row * APAD + col]           = rtf32(v0 * scale);
                    qb[row * APAD + col + 1]       = rtf32(v1 * scale);
                    qb[(row + 8) * APAD + col]     = rtf32(v2 * scale);
                    qb[(row + 8) * APAD + col + 1] = rtf32(v3 * scale);
                } else if (cidx == 1) {
                    kb[row * APAD + col]           = rtf32(v0);
                    kb[row * APAD + col + 1]       = rtf32(v1);
                    kb[(row + 8) * APAD + col]     = rtf32(v2);
                    kb[(row + 8) * APAD + col + 1] = rtf32(v3);
                } else {
                    vt[col * VTP + row]           = rtf32(v0);
                    vt[(col + 1) * VTP + row]     = rtf32(v1);
                    vt[col * VTP + row + 8]       = rtf32(v2);
                    vt[(col + 1) * VTP + row + 8] = rtf32(v3);
                }
            }
        }
        __syncthreads();
    }

    // ---- scores: all 4 heads, 2 warps each (64x64x32 per head) ----
    {
        int h = wid >> 1;
        int hoff = h * HD;
        int rbase = (wid & 1) * 32;
        float acc[2][8][4];
        #pragma unroll
        for (int m = 0; m < 2; m++)
            #pragma unroll
            for (int n = 0; n < 8; n++)
                #pragma unroll
                for (int q = 0; q < 4; q++) acc[m][n][q] = 0.f;
        wgemm<2, 8, 4>(qb, APAD, hoff, kb, APAD, hoff, acc, rbase, 0, g, i);

        float* sbh = sb4 + h * (64 * SBP);
        const float* gb = g_bias + h * 4096;
        #pragma unroll
        for (int m = 0; m < 2; m++) {
            int row0 = rbase + m * 16 + g;
            int r0 = regid[row0];
            int r1 = regid[row0 + 8];
            #pragma unroll
            for (int n = 0; n < 8; n++) {
                int col = n * 8 + 2 * i;
                int c0 = regid[col], c1 = regid[col + 1];
                float m00 = (r0 != c0) ? -100.f : 0.f;
                float m01 = (r0 != c1) ? -100.f : 0.f;
                float m10 = (r1 != c0) ? -100.f : 0.f;
                float m11 = (r1 != c1) ? -100.f : 0.f;
                sbh[row0 * SBP + col]           = acc[m][n][0] + gb[row0 * 64 + col] + m00;
                sbh[row0 * SBP + col + 1]       = acc[m][n][1] + gb[row0 * 64 + col + 1] + m01;
                sbh[(row0 + 8) * SBP + col]     = acc[m][n][2] + gb[(row0 + 8) * 64 + col] + m10;
                sbh[(row0 + 8) * SBP + col + 1] = acc[m][n][3] + gb[(row0 + 8) * 64 + col + 1] + m11;
            }
        }
    }
    __syncthreads();

    // ---- softmax: one thread per (head, row) ----
    {
        float* rowp = sb4 + (tid >> 6) * (64 * SBP) + (tid & 63) * SBP;
        float mx = -1e30f;
        #pragma unroll 8
        for (int j = 0; j < 64; j++) mx = fmaxf(mx, rowp[j]);
        float s = 0.f;
        #pragma unroll 8
        for (int j = 0; j < 64; j++) {
            float e = __expf(rowp[j] - mx);
            s += e;
            rowp[j] = rtf32(e);
        }
        rsum4[tid] = 1.0f / s;
    }
    __syncthreads();

    // ---- PV: per head 64x32x64, 2 warps each ----
    {
        int h = wid >> 1;
        int hoff = h * HD;
        int rbase = (wid & 1) * 32;
        float acc[2][4][4];
        #pragma unroll
        for (int m = 0; m < 2; m++)
            #pragma unroll
            for (int n = 0; n < 4; n++)
                #pragma unroll
                for (int q = 0; q < 4; q++) acc[m][n][q] = 0.f;
        wgemm<2, 4, 8>(sb4 + h * (64 * SBP), SBP, 0, vt, VTP, 0, acc, rbase, hoff, g, i);

        #pragma unroll
        for (int m = 0; m < 2; m++) {
            int row = rbase + m * 16 + g;
            float rs0 = rsum4[h * 64 + row];
            float rs1 = rsum4[h * 64 + row + 8];
            #pragma unroll
            for (int n = 0; n < 4; n++) {
                int col = hoff + n * 8 + 2 * i;
                ow[row * APAD + col]           = rtf32(acc[m][n][0] * rs0);
                ow[row * APAD + col + 1]       = rtf32(acc[m][n][1] * rs0);
                ow[(row + 8) * APAD + col]     = rtf32(acc[m][n][2] * rs1);
                ow[(row + 8) * APAD + col + 1] = rtf32(acc[m][n][3] * rs1);
            }
        }
    }
    __syncthreads();

    // ---- stage proj_w (overwrites sb4 tail region) ----
    #pragma unroll
    for (int it = 0; it < 16; it++) {
        int e4 = tid + 256 * it;
        int r = e4 >> 5;
        int c = (e4 & 31) << 2;
        float4 v = *(const float4*)(proj_w + r * DIM + c);
        float* d = wb + r * APAD + c;
        d[0] = rtf32(v.x); d[1] = rtf32(v.y); d[2] = rtf32(v.z); d[3] = rtf32(v.w);
    }
    __syncthreads();

    // ---- proj GEMM 64x128x128 -> kb (fp32) ----
    {
        float acc[2][4][4];
        #pragma unroll
        for (int m = 0; m < 2; m++)
            #pragma unroll
            for (int n = 0; n < 4; n++)
                #pragma unroll
                for (int q = 0; q < 4; q++) acc[m][n][q] = 0.f;
        int rbase = (wid >> 2) * 32;
        int nbase = (wid & 3) * 32;
        wgemm<2, 4, 16>(ow, APAD, 0, wb, APAD, 0, acc, rbase, nbase, g, i);
        #pragma unroll
        for (int n = 0; n < 4; n++) {
            int col = nbase + n * 8 + 2 * i;
            float b0f = proj_b[col];
            float b1f = proj_b[col + 1];
            #pragma unroll
            for (int m = 0; m < 2; m++) {
                int row = rbase + m * 16 + g;
                kb[row * APAD + col]           = acc[m][n][0] + b0f;
                kb[row * APAD + col + 1]       = acc[m][n][1] + b1f;
                kb[(row + 8) * APAD + col]     = acc[m][n][2] + b0f;
                kb[(row + 8) * APAD + col + 1] = acc[m][n][3] + b1f;
            }
        }
    }
    __syncthreads();

    // ---- LN1 stats (4 threads per row) ----
    if (tid < 256) {
        int row = tid >> 2;
        int cb = (tid & 3) * 32;
        float s = 0.f;
        #pragma unroll 8
        for (int c = 0; c < 32; c++) s += kb[row * APAD + cb + c];
        rsum4[tid] = s;   // reuse as partials
    }
    __syncthreads();
    if (tid < 64) {
        float s = rsum4[4 * tid] + rsum4[4 * tid + 1] + rsum4[4 * tid + 2] + rsum4[4 * tid + 3];
        mu[tid] = s * (1.0f / DIM);
    }
    __syncthreads();
    {
        int row = tid >> 2;
        int cb = (tid & 3) * 32;
        float m = mu[row];
        float v = 0.f;
        #pragma unroll 8
        for (int c = 0; c < 32; c++) {
            float d = kb[row * APAD + cb + c] - m;
            v += d * d;
        }
        rsum4[tid] = v;
    }
    __syncthreads();
    if (tid < 64) {
        float v = rsum4[4 * tid] + rsum4[4 * tid + 1] + rsum4[4 * tid + 2] + rsum4[4 * tid + 3];
        rstd[tid] = rsqrtf(v * (1.0f / DIM) + 1e-5f);
    }
    __syncthreads();

    // ---- y = x + LN(proj) ----
    float* yb = g_ybuf + (size_t)bimg * (LSEQ * DIM);
    #pragma unroll
    for (int it = 0; it < 8; it++) {
        int e4 = tid + 256 * it;
        int t = e4 >> 5;
        int c = (e4 & 31) << 2;
        int ti = t >> 3, tj = t & 7;
        int hh = (wh * 8 + ti + 4) & 63;
        int wwp = (ww * 8 + tj + 4) & 63;
        size_t goff = (size_t)((hh << 6) + wwp) * DIM + c;
        float4 xv = *(const float4*)(xbase + goff);
        float m = mu[t], r = rstd[t];
        float4 o;
        o.x = xv.x + (kb[t * APAD + c + 0] - m) * r * n1w[c + 0] + n1b[c + 0];
        o.y = xv.y + (kb[t * APAD + c + 1] - m) * r * n1w[c + 1] + n1b[c + 1];
        o.z = xv.z + (kb[t * APAD + c + 2] - m) * r * n1w[c + 2] + n1b[c + 2];
        o.w = xv.w + (kb[t * APAD + c + 3] - m) * r * n1w[c + 3] + n1b[c + 3];
        *(float4*)(yb + goff) = o;
    }
}

// ---------------- Kernel 3: fused MLP + LN2 + residual (tf32, unchanged from R2) ----------------
__global__ __launch_bounds__(256, 1) void mlp_kernel(
    const float* __restrict__ fc1w, const float* __restrict__ fc1b,
    const float* __restrict__ fc2w, const float* __restrict__ fc2b,
    const float* __restrict__ n2w, const float* __restrict__ n2b,
    float* __restrict__ out)
{
    extern __shared__ float sm[];
    float* Ysm = sm;
    float* Wsm = Ysm + 128 * APAD;
    float* Hsm = Wsm + 128 * APAD;
    float* ps  = Hsm + 128 * APAD;
    float* muv = ps + 256;
    float* rsv = muv + 128;

    int tid = threadIdx.x;
    int wid = tid >> 5;
    int lane = tid & 31;
    int g = lane >> 2;
    int i = lane & 3;
    int rbase = (wid >> 1) * 32;
    int nbase = (wid & 1) * 64;

    size_t tok0 = (size_t)blockIdx.x * 128;
    const float* ysrc = g_ybuf + tok0 * DIM;

    #pragma unroll
    for (int it = 0; it < 16; it++) {
        int e4 = tid + 256 * it;
        int t = e4 >> 5;
        int c = (e4 & 31) << 2;
        float4 v = *(const float4*)(ysrc + (size_t)t * DIM + c);
        float* d = Ysm + t * APAD + c;
        d[0] = v.x; d[1] = v.y; d[2] = v.z; d[3] = v.w;
    }

    float acc2[2][8][4];
    #pragma unroll
    for (int m = 0; m < 2; m++)
        #pragma unroll
        for (int n = 0; n < 8; n++)
            #pragma unroll
            for (int q = 0; q < 4; q++) acc2[m][n][q] = 0.f;

    for (int hc = 0; hc < 4; hc++) {
        __syncthreads();
        const float* w1 = fc1w + (size_t)hc * 128 * DIM;
        #pragma unroll
        for (int it = 0; it < 16; it++) {
            int e4 = tid + 256 * it;
            int r = e4 >> 5;
            int c = (e4 & 31) << 2;
            float4 v = *(const float4*)(w1 + r * DIM + c);
            float* d = Wsm + r * APAD + c;
            d[0] = rtf32(v.x); d[1] = rtf32(v.y); d[2] = rtf32(v.z); d[3] = rtf32(v.w);
        }
        __syncthreads();

        float acc1[2][8][4];
        #pragma unroll
        for (int m = 0; m < 2; m++)
            #pragma unroll
            for (int n = 0; n < 8; n++)
                #pragma unroll
                for (int q = 0; q < 4; q++) acc1[m][n][q] = 0.f;
        // A = Y (fp32, convert on the fly via bit-load of rounded? Y kept exact; cvt here)
        #pragma unroll
        for (int ks = 0; ks < 16; ks++) {
            int kc = i + ks * 8;
            uint32_t a[2][4];
            #pragma unroll
            for (int m = 0; m < 2; m++) {
                int r0 = rbase + m * 16 + g;
                a[m][0] = f2tf32(Ysm[r0 * APAD + kc]);
                a[m][1] = f2tf32(Ysm[(r0 + 8) * APAD + kc]);
                a[m][2] = f2tf32(Ysm[r0 * APAD + kc + 4]);
                a[m][3] = f2tf32(Ysm[(r0 + 8) * APAD + kc + 4]);
            }
            #pragma unroll
            for (int n = 0; n < 8; n++) {
                int nc = nbase + n * 8 + g;
                uint32_t b0 = __float_as_uint(Wsm[nc * APAD + kc]);
                uint32_t b1 = __float_as_uint(Wsm[nc * APAD + kc + 4]);
                mma_tf32(acc1[0][n], a[0], b0, b1);
                mma_tf32(acc1[1][n], a[1], b0, b1);
            }
        }

        const float is2 = 0.70710678118654752f;
        #pragma unroll
        for (int n = 0; n < 8; n++) {
            int col = nbase + n * 8 + 2 * i;
            float b0f = fc1b[hc * 128 + col];
            float b1f = fc1b[hc * 128 + col + 1];
            #pragma unroll
            for (int m = 0; m < 2; m++) {
                int row = rbase + m * 16 + g;
                float v0 = acc1[m][n][0] + b0f;
                float v1 = acc1[m][n][1] + b1f;
                float v2 = acc1[m][n][2] + b0f;
                float v3 = acc1[m][n][3] + b1f;
                v0 = 0.5f * v0 * (1.0f + erff(v0 * is2));
                v1 = 0.5f * v1 * (1.0f + erff(v1 * is2));
                v2 = 0.5f * v2 * (1.0f + erff(v2 * is2));
                v3 = 0.5f * v3 * (1.0f + erff(v3 * is2));
                Hsm[row * APAD + col]           = rtf32(v0);
                Hsm[row * APAD + col + 1]       = rtf32(v1);
                Hsm[(row + 8) * APAD + col]     = rtf32(v2);
                Hsm[(row + 8) * APAD + col + 1] = rtf32(v3);
            }
        }
        __syncthreads();

        #pragma unroll
        for (int it = 0; it < 16; it++) {
            int e4 = tid + 256 * it;
            int r = e4 >> 5;
            int c = (e4 & 31) << 2;
            float4 v = *(const float4*)(fc2w + (size_t)r * 512 + hc * 128 + c);
            float* d = Wsm + r * APAD + c;
            d[0] = rtf32(v.x); d[1] = rtf32(v.y); d[2] = rtf32(v.z); d[3] = rtf32(v.w);
        }
        __syncthreads();

        wgemm<2, 8, 16>(Hsm, APAD, 0, Wsm, APAD, 0, acc2, rbase, nbase, g, i);
    }

    __syncthreads();
    #pragma unroll
    for (int n = 0; n < 8; n++) {
        int col = nbase + n * 8 + 2 * i;
        float b0f = fc2b[col];
        float b1f = fc2b[col + 1];
        #pragma unroll
        for (int m = 0; m < 2; m++) {
            int row = rbase + m * 16 + g;
            Hsm[row * APAD + col]           = acc2[m][n][0] + b0f;
            Hsm[row * APAD + col + 1]       = acc2[m][n][1] + b1f;
            Hsm[(row + 8) * APAD + col]     = acc2[m][n][2] + b0f;
            Hsm[(row + 8) * APAD + col + 1] = acc2[m][n][3] + b1f;
        }
    }
    __syncthreads();

    {
        int row = tid >> 1;
        int cb = (tid & 1) * 64;
        float s = 0.f;
        #pragma unroll 8
        for (int c = 0; c < 64; c++) s += Hsm[row * APAD + cb + c];
        ps[tid] = s;
    }
    __syncthreads();
    if (tid < 128) muv[tid] = (ps[2 * tid] + ps[2 * tid + 1]) * (1.0f / DIM);
    __syncthreads();
    {
        int row = tid >> 1;
        int cb = (tid & 1) * 64;
        float m = muv[row];
        float v = 0.f;
        #pragma unroll 8
        for (int c = 0; c < 64; c++) {
            float d = Hsm[row * APAD + cb + c] - m;
            v += d * d;
        }
        ps[tid] = v;
    }
    __syncthreads();
    if (tid < 128) rsv[tid] = rsqrtf((ps[2 * tid] + ps[2 * tid + 1]) * (1.0f / DIM) + 1e-5f);
    __syncthreads();

    float* od = out + tok0 * DIM;
    #pragma unroll
    for (int it = 0; it < 16; it++) {
        int e4 = tid + 256 * it;
        int t = e4 >> 5;
        int c = (e4 & 31) << 2;
        float m = muv[t], r = rsv[t];
        float4 o;
        o.x = Ysm[t * APAD + c + 0] + (Hsm[t * APAD + c + 0] - m) * r * n2w[c + 0] + n2b[c + 0];
        o.y = Ysm[t * APAD + c + 1] + (Hsm[t * APAD + c + 1] - m) * r * n2w[c + 1] + n2b[c + 1];
        o.z = Ysm[t * APAD + c + 2] + (Hsm[t * APAD + c + 2] - m) * r * n2w[c + 2] + n2b[c + 2];
        o.w = Ysm[t * APAD + c + 3] + (Hsm[t * APAD + c + 3] - m) * r * n2w[c + 3] + n2b[c + 3];
        *(float4*)(od + (size_t)t * DIM + c) = o;
    }
}

static const int ATTN_SMEM = (50944 + 256 + 64 + 64 + 64) * 4;
static const int MLP_SMEM  = (3 * 128 * APAD + 256 + 128 + 128) * 4;

extern "C" void kernel_launch(void* const* d_in, const int* in_sizes, int n_in,
                              void* d_out, int out_size) {
    const float* x      = (const float*)d_in[0];
    const float* qkv_w  = (const float*)d_in[1];
    const float* qkv_b  = (const float*)d_in[2];
    const float* proj_w = (const float*)d_in[3];
    const float* proj_b = (const float*)d_in[4];
    const float* rpe_w1 = (const float*)d_in[5];
    const float* rpe_b1 = (const float*)d_in[6];
    const float* rpe_w2 = (const float*)d_in[7];
    const float* n1w    = (const float*)d_in[8];
    const float* n1b    = (const float*)d_in[9];
    const float* fc1w   = (const float*)d_in[10];
    const float* fc1b   = (const float*)d_in[11];
    const float* fc2w   = (const float*)d_in[12];
    const float* fc2b   = (const float*)d_in[13];
    const float* n2w    = (const float*)d_in[14];
    const float* n2b    = (const float*)d_in[15];
    float* out = (float*)d_out;

    cudaFuncSetAttribute(attn_kernel, cudaFuncAttributeMaxDynamicSharedMemorySize, ATTN_SMEM);
    cudaFuncSetAttribute(mlp_kernel,  cudaFuncAttributeMaxDynamicSharedMemorySize, MLP_SMEM);

    bias_table_kernel<<<225, 128>>>(rpe_w1, rpe_b1, rpe_w2);
    bias_scatter_kernel<<<64, 256>>>();
    attn_kernel<<<2048, 256, ATTN_SMEM>>>(x, qkv_w, qkv_b, proj_w, proj_b, n1w, n1b);
    mlp_kernel<<<1024, 256, MLP_SMEM>>>(fc1w, fc1b, fc2w, fc2b, n2w, n2b, out);
}